// round 2
// baseline (speedup 1.0000x reference)
#include <cuda_runtime.h>
#include <math.h>

// ---------------- problem constants ----------------
#define BB   512
#define SS   128
#define EE   640
#define AA   129
#define HH   2048
#define NH   10
#define HD   64
#define KWIN 64
#define BS   (BB*SS)          // 65536
#define KFLAT (EE*SS)         // 81920
#define LDW1 (KFLAT + AA)     // 82049

// ---------------- scratch (device globals, no allocs) ----------------
__device__ float g_h[BS * EE];          // 41.9M floats
__device__ float g_qkv[BS * 3 * EE];    // 125.8M floats (reused as attn_out)
__device__ float g_ctx[BS * EE];        // 41.9M floats (reused as x_flat)
__device__ float g_t1[BB * HH];
__device__ float g_t2[BB * HH];
__device__ float g_t3[BB * (HH/2)];
__device__ float g_t4[BB * (HH/4)];
__device__ float g_t5[BB * AA];

// ================= generic fp32 GEMM: C = A(MxK) * W(NxK)^T + bias =================
// EPI: 0 = bias only, 1 = relu(bias+), 2 = relu(bias+) + Res
template<int BM, int BN, int BK, int TM, int TN, int EPI>
__global__ void __launch_bounds__((BM/TM)*(BN/TN))
gemm_tn(const float* __restrict__ A, int lda,
        const float* __restrict__ W, int ldw,
        const float* __restrict__ bias,
        const float* __restrict__ Res,
        float* __restrict__ C,
        int M, int N, int K)
{
    constexpr int THREADS = (BM/TM)*(BN/TN);
    constexpr int KV = BK / 4;
    __shared__ __align__(16) float As[BK][BM];
    __shared__ __align__(16) float Ws[BK][BN];

    const int tid = threadIdx.x;
    const int m0 = blockIdx.y * BM;
    const int n0 = blockIdx.x * BN;
    const int tnx = tid % (BN/TN);
    const int tmy = tid / (BN/TN);

    const bool a_al = ((lda & 3) == 0);
    const bool w_al = ((ldw & 3) == 0);

    float acc[TM][TN];
#pragma unroll
    for (int i = 0; i < TM; i++)
#pragma unroll
        for (int j = 0; j < TN; j++) acc[i][j] = 0.f;

    for (int k0 = 0; k0 < K; k0 += BK) {
        // ---- load A tile (BM x BK), store transposed As[k][m]
#pragma unroll
        for (int it = 0; it < (BM*KV)/THREADS; it++) {
            int v = tid + it * THREADS;
            int row = v / KV, kq = v % KV;
            float4 f = make_float4(0.f,0.f,0.f,0.f);
            int m = m0 + row;
            if (m < M) {
                const float* p = A + (size_t)m * lda + k0 + kq*4;
                if (a_al) f = *reinterpret_cast<const float4*>(p);
                else { f.x = p[0]; f.y = p[1]; f.z = p[2]; f.w = p[3]; }
            }
            As[kq*4+0][row] = f.x; As[kq*4+1][row] = f.y;
            As[kq*4+2][row] = f.z; As[kq*4+3][row] = f.w;
        }
        // ---- load W tile (BN x BK), store transposed Ws[k][n]
#pragma unroll
        for (int it = 0; it < (BN*KV)/THREADS; it++) {
            int v = tid + it * THREADS;
            int row = v / KV, kq = v % KV;
            float4 f = make_float4(0.f,0.f,0.f,0.f);
            int n = n0 + row;
            if (n < N) {
                const float* p = W + (size_t)n * ldw + k0 + kq*4;
                if (w_al) f = *reinterpret_cast<const float4*>(p);
                else { f.x = p[0]; f.y = p[1]; f.z = p[2]; f.w = p[3]; }
            }
            Ws[kq*4+0][row] = f.x; Ws[kq*4+1][row] = f.y;
            Ws[kq*4+2][row] = f.z; Ws[kq*4+3][row] = f.w;
        }
        __syncthreads();

#pragma unroll
        for (int kk = 0; kk < BK; kk++) {
            float a[TM], w[TN];
#pragma unroll
            for (int i = 0; i < TM/4; i++) {
                float4 t = *reinterpret_cast<const float4*>(&As[kk][tmy*TM + i*4]);
                a[i*4+0]=t.x; a[i*4+1]=t.y; a[i*4+2]=t.z; a[i*4+3]=t.w;
            }
#pragma unroll
            for (int j = 0; j < TN/4; j++) {
                float4 t = *reinterpret_cast<const float4*>(&Ws[kk][tnx*TN + j*4]);
                w[j*4+0]=t.x; w[j*4+1]=t.y; w[j*4+2]=t.z; w[j*4+3]=t.w;
            }
#pragma unroll
            for (int i = 0; i < TM; i++)
#pragma unroll
                for (int j = 0; j < TN; j++) acc[i][j] += a[i] * w[j];
        }
        __syncthreads();
    }

#pragma unroll
    for (int i = 0; i < TM; i++) {
        int m = m0 + tmy*TM + i;
        if (m >= M) continue;
#pragma unroll
        for (int j = 0; j < TN; j++) {
            int n = n0 + tnx*TN + j;
            if (n >= N) continue;
            float v = acc[i][j] + bias[n];
            if (EPI == 1) v = fmaxf(v, 0.f);
            if (EPI == 2) v = fmaxf(v, 0.f) + Res[(size_t)m * N + n];
            C[(size_t)m * N + n] = v;
        }
    }
}

// ================= attention: one block per (batch, head) =================
#define ATTN_SMEM ((3*128*65 + 128*129)*4)
__global__ void __launch_bounds__(128)
attn_kernel(const float* __restrict__ qkv, float* __restrict__ ctx)
{
    const int b = blockIdx.x / NH;
    const int h = blockIdx.x % NH;
    extern __shared__ float sm[];
    float* qs = sm;                    // [128][65]
    float* ks = sm + 128*65;
    float* vs = sm + 2*128*65;
    float* sc = sm + 3*128*65;         // [128][129]
    const int tid = threadIdx.x;       // 128 threads

    const size_t base = (size_t)b * SS * (3*EE) + (size_t)h * HD;
    for (int idx = tid; idx < SS*HD; idx += 128) {
        int s = idx >> 6, d = idx & 63;
        const float* p = qkv + base + (size_t)s * (3*EE);
        qs[s*65 + d] = p[d] * 0.125f;      // HD^-0.5
        ks[s*65 + d] = p[EE + d];
        vs[s*65 + d] = p[2*EE + d];
    }
    __syncthreads();

    float qreg[HD];
#pragma unroll
    for (int d = 0; d < HD; d++) qreg[d] = qs[tid*65 + d];

    float mx = -1e30f;
    for (int j = 0; j < SS; j++) {
        float s = 0.f;
#pragma unroll
        for (int d = 0; d < HD; d++) s += qreg[d] * ks[j*65 + d];
        sc[tid*129 + j] = s;
        mx = fmaxf(mx, s);
    }
    float sum = 0.f;
    for (int j = 0; j < SS; j++) {
        float e = expf(sc[tid*129 + j] - mx);
        sc[tid*129 + j] = e;
        sum += e;
    }
    const float inv = 1.f / sum;

    float acc[HD];
#pragma unroll
    for (int d = 0; d < HD; d++) acc[d] = 0.f;
    for (int j = 0; j < SS; j++) {
        float w = sc[tid*129 + j] * inv;
#pragma unroll
        for (int d = 0; d < HD; d++) acc[d] += w * vs[j*65 + d];
    }
    float* outp = ctx + ((size_t)b * SS + tid) * EE + h * HD;
#pragma unroll
    for (int d = 0; d < HD; d++) outp[d] = acc[d];
}

// ================= block reduce =================
__device__ __forceinline__ float block_reduce_sum(float v)
{
    __shared__ float shm[32];
    int lane = threadIdx.x & 31, wid = threadIdx.x >> 5;
#pragma unroll
    for (int o = 16; o > 0; o >>= 1) v += __shfl_down_sync(0xffffffffu, v, o);
    if (lane == 0) shm[wid] = v;
    __syncthreads();
    float r = (threadIdx.x < (blockDim.x >> 5)) ? shm[threadIdx.x] : 0.f;
    if (wid == 0) {
#pragma unroll
        for (int o = 16; o > 0; o >>= 1) r += __shfl_down_sync(0xffffffffu, r, o);
        if (lane == 0) shm[0] = r;
    }
    __syncthreads();
    r = shm[0];
    __syncthreads();
    return r;
}

// ================= layernorm (optionally fused residual add) =================
template<bool ADD>
__global__ void ln_kernel(const float* __restrict__ X, const float* __restrict__ Y,
                          const float* __restrict__ g, const float* __restrict__ be,
                          float* __restrict__ out, int D)
{
    const size_t row = blockIdx.x;
    const float* x = X + row * D;
    const float* y = ADD ? (Y + row * D) : nullptr;
    float s = 0.f, s2 = 0.f;
    for (int i = threadIdx.x; i < D; i += blockDim.x) {
        float v = x[i];
        if (ADD) v += y[i];
        s += v; s2 += v * v;
    }
    float S  = block_reduce_sum(s);
    float S2 = block_reduce_sum(s2);
    float mean = S / (float)D;
    float var  = S2 / (float)D - mean * mean;
    float inv  = rsqrtf(var + 1e-5f);
    for (int i = threadIdx.x; i < D; i += blockDim.x) {
        float v = x[i];
        if (ADD) v += y[i];
        out[row * D + i] = (v - mean) * inv * g[i] + be[i];
    }
}

// ================= fc1 tail (last_action columns) + ReLU =================
__global__ void fc1_fix_kernel(float* __restrict__ t1, const float* __restrict__ la,
                               const float* __restrict__ w1)
{
    const int b = blockIdx.y;
    const int n = blockIdx.x * blockDim.x + threadIdx.x;
    __shared__ float las[AA];
    if (threadIdx.x < AA) las[threadIdx.x] = la[b * AA + threadIdx.x];
    __syncthreads();
    const float* w = w1 + (size_t)n * LDW1 + KFLAT;
    float acc = 0.f;
    for (int j = 0; j < AA; j++) acc += las[j] * w[j];
    size_t idx = (size_t)b * HH + n;
    t1[idx] = fmaxf(t1[idx] + acc, 0.f);
}

// ================= fc6 + top-K mask + masked softmax =================
__global__ void head_kernel(const float* __restrict__ t5, const float* __restrict__ la,
                            const float* __restrict__ w6, const float* __restrict__ b6,
                            float* __restrict__ out)
{
    const int b = blockIdx.x;
    __shared__ float cat[2*AA];
    __shared__ float sc[AA];
    __shared__ float red[256];
    const int tid = threadIdx.x;   // 256

    // FIX: 2*AA = 258 > blockDim (256) — must use a strided loop, the old
    // single-guard load left cat[256..257] (la[127..128]) uninitialized.
    for (int i = tid; i < 2*AA; i += 256) {
        cat[i] = (i < AA) ? t5[b*AA + i] : la[b*AA + (i - AA)];
    }
    __syncthreads();

    if (tid < AA) {
        float a = b6[tid];
        const float* w = w6 + tid * (2*AA);
        for (int j = 0; j < 2*AA; j++) a += w[j] * cat[j];
        sc[tid] = a;
    }
    __syncthreads();

    bool winner = false; float v = 0.f;
    if (tid < AA) {
        v = sc[tid];
        int cnt = 0;
        for (int j = 0; j < AA; j++) {
            float u = sc[j];
            cnt += (u > v) || (u == v && j < tid);
        }
        winner = cnt < KWIN;   // exact jax.lax.top_k tie-break (lowest index)
    }
    // max over winners
    red[tid] = (tid < AA && winner) ? v : -1e30f;
    __syncthreads();
    for (int s = 128; s > 0; s >>= 1) {
        if (tid < s) red[tid] = fmaxf(red[tid], red[tid + s]);
        __syncthreads();
    }
    float mx = red[0];
    __syncthreads();
    // sum of exp over winners (losers: exp(v-1e9-mx) underflows to exactly 0)
    float e = (tid < AA && winner) ? expf(v - mx) : 0.f;
    red[tid] = e;
    __syncthreads();
    for (int s = 128; s > 0; s >>= 1) {
        if (tid < s) red[tid] += red[tid + s];
        __syncthreads();
    }
    float inv = 1.f / red[0];
    if (tid < AA) out[b*AA + tid] = e * inv;
}

// ================= launcher =================
extern "C" void kernel_launch(void* const* d_in, const int* in_sizes, int n_in,
                              void* d_out, int out_size)
{
    const float* hist      = (const float*)d_in[0];
    const float* la        = (const float*)d_in[1];
    const float* embed_w   = (const float*)d_in[2];
    const float* embed_b   = (const float*)d_in[3];
    const float* in_proj_w = (const float*)d_in[4];
    const float* in_proj_b = (const float*)d_in[5];
    const float* out_proj_w= (const float*)d_in[6];
    const float* out_proj_b= (const float*)d_in[7];
    const float* lnorm_g   = (const float*)d_in[8];
    const float* lnorm_b   = (const float*)d_in[9];
    const float* fc1_w     = (const float*)d_in[10];
    const float* fc1_b     = (const float*)d_in[11];
    const float* fc2_w     = (const float*)d_in[12];
    const float* fc2_b     = (const float*)d_in[13];
    const float* ln1_g     = (const float*)d_in[14];
    const float* ln1_b     = (const float*)d_in[15];
    const float* fc3_w     = (const float*)d_in[16];
    const float* fc3_b     = (const float*)d_in[17];
    const float* fc4_w     = (const float*)d_in[18];
    const float* fc4_b     = (const float*)d_in[19];
    const float* fc5_w     = (const float*)d_in[20];
    const float* fc5_b     = (const float*)d_in[21];
    const float* fc6_w     = (const float*)d_in[22];
    const float* fc6_b     = (const float*)d_in[23];
    float* out = (float*)d_out;

    float *h, *qkv, *ctx, *t1, *t2, *t3, *t4, *t5;
    cudaGetSymbolAddress((void**)&h,   g_h);
    cudaGetSymbolAddress((void**)&qkv, g_qkv);
    cudaGetSymbolAddress((void**)&ctx, g_ctx);
    cudaGetSymbolAddress((void**)&t1,  g_t1);
    cudaGetSymbolAddress((void**)&t2,  g_t2);
    cudaGetSymbolAddress((void**)&t3,  g_t3);
    cudaGetSymbolAddress((void**)&t4,  g_t4);
    cudaGetSymbolAddress((void**)&t5,  g_t5);

    // 1) embed: h = hist @ embed_w^T + b     [65536,640]
    gemm_tn<128,128,16,8,8,0><<<dim3(EE/128, BS/128), 256>>>(
        hist, EE, embed_w, EE, embed_b, nullptr, h, BS, EE, EE);

    // 2) qkv = h @ in_proj_w^T + b           [65536,1920]
    gemm_tn<128,128,16,8,8,0><<<dim3((3*EE)/128, BS/128), 256>>>(
        h, EE, in_proj_w, EE, in_proj_b, nullptr, qkv, BS, 3*EE, EE);

    // 3) attention -> ctx                    [65536,640]
    cudaFuncSetAttribute(attn_kernel, cudaFuncAttributeMaxDynamicSharedMemorySize, ATTN_SMEM);
    attn_kernel<<<BB*NH, 128, ATTN_SMEM>>>(qkv, ctx);

    // 4) attn_out = ctx @ out_proj_w^T + b  (reuse qkv buffer)
    gemm_tn<128,128,16,8,8,0><<<dim3(EE/128, BS/128), 256>>>(
        ctx, EE, out_proj_w, EE, out_proj_b, nullptr, qkv, BS, EE, EE);

    // 5) x = LN(attn_out + h) -> x_flat (reuse ctx buffer)
    ln_kernel<true><<<BS, 256>>>(qkv, h, lnorm_g, lnorm_b, ctx, EE);

    // 6) fc1 main part over K=81920 (ldw = 82049, scalar-path), bias, no relu yet
    gemm_tn<64,64,16,4,4,0><<<dim3(HH/64, BB/64), 256>>>(
        ctx, KFLAT, fc1_w, LDW1, fc1_b, nullptr, t1, BB, HH, KFLAT);

    // 7) fc1 last_action tail + relu
    fc1_fix_kernel<<<dim3(HH/256, BB), 256>>>(t1, la, fc1_w);

    // 8) fc2: t2 = relu(t1 @ fc2^T + b) + t1
    gemm_tn<64,64,16,4,4,2><<<dim3(HH/64, BB/64), 256>>>(
        t1, HH, fc2_w, HH, fc2_b, t1, t2, BB, HH, HH);

    // 9) ln1 in-place on t2
    ln_kernel<false><<<BB, 256>>>(t2, nullptr, ln1_g, ln1_b, t2, HH);

    // 10) fc3 relu                            [512,1024]
    gemm_tn<64,64,16,4,4,1><<<dim3((HH/2)/64, BB/64), 256>>>(
        t2, HH, fc3_w, HH, fc3_b, nullptr, t3, BB, HH/2, HH);

    // 11) fc4 relu                            [512,512]
    gemm_tn<64,64,16,4,4,1><<<dim3((HH/4)/64, BB/64), 256>>>(
        t3, HH/2, fc4_w, HH/2, fc4_b, nullptr, t4, BB, HH/4, HH/2);

    // 12) fc5                                  [512,129]
    gemm_tn<64,64,16,4,4,0><<<dim3((AA+63)/64, BB/64), 256>>>(
        t4, HH/4, fc5_w, HH/4, fc5_b, nullptr, t5, BB, AA, HH/4);

    // 13) fc6 + top-K + masked softmax -> out [512,129]
    head_kernel<<<BB, 256>>>(t5, la, fc6_w, fc6_b, out);
}

// round 5
// speedup vs baseline: 1.6090x; 1.6090x over previous
#include <cuda_runtime.h>
#include <cstdint>
#include <math.h>

// ---------------- problem constants ----------------
#define BB   512
#define SS   128
#define EE   640
#define AA   129
#define HH   2048
#define NH   10
#define HD   64
#define KWIN 64
#define BS   (BB*SS)          // 65536
#define KFLAT (EE*SS)         // 81920
#define LDW1 (KFLAT + AA)     // 82049
#define FC1_SPLITS 8
#define FC1_KLOC   (KFLAT/FC1_SPLITS)   // 10240

// ---------------- scratch (device globals, no allocs) ----------------
__device__ float g_h[BS * EE];          // h; later reused as fc1 split-K partials
__device__ float g_qkv[BS * 3 * EE];    // qkv; reused as attn_out
__device__ float g_ctx[BS * EE];        // ctx; reused as x_flat
__device__ float g_t1[BB * HH];
__device__ float g_t2[BB * HH];
__device__ float g_t3[BB * (HH/2)];
__device__ float g_t4[BB * (HH/4)];
__device__ float g_t5[BB * AA];

// ================= helpers =================
__device__ __forceinline__ uint32_t f2tf32(float x) {
    uint32_t r; asm("cvt.rna.tf32.f32 %0, %1;" : "=r"(r) : "f"(x)); return r;
}
#define MMA_TF32(c, a, b) \
    asm volatile("mma.sync.aligned.m16n8k8.row.col.f32.tf32.tf32.f32 " \
        "{%0,%1,%2,%3}, {%4,%5,%6,%7}, {%8,%9}, {%0,%1,%2,%3};" \
        : "+f"((c)[0]), "+f"((c)[1]), "+f"((c)[2]), "+f"((c)[3]) \
        : "r"((a)[0]), "r"((a)[1]), "r"((a)[2]), "r"((a)[3]), \
          "r"((b)[0]), "r"((b)[1]))

// split fp32 -> (hi,lo) tf32 and store to smem (16B vectors)
__device__ __forceinline__ void splitStore(float4 f, float* hi, float* lo, int off) {
    float h0 = __uint_as_float(f2tf32(f.x));
    float h1 = __uint_as_float(f2tf32(f.y));
    float h2 = __uint_as_float(f2tf32(f.z));
    float h3 = __uint_as_float(f2tf32(f.w));
    float4 hv = make_float4(h0, h1, h2, h3);
    float4 lv = make_float4(
        __uint_as_float(f2tf32(f.x - h0)),
        __uint_as_float(f2tf32(f.y - h1)),
        __uint_as_float(f2tf32(f.z - h2)),
        __uint_as_float(f2tf32(f.w - h3)));
    *reinterpret_cast<float4*>(hi + off) = hv;
    *reinterpret_cast<float4*>(lo + off) = lv;
}

// ============== 3xTF32 mma.sync GEMM:  C = A(M,K) @ W(N,K)^T ==============
// EPI: 0 bias | 1 bias+relu | 2 relu(bias+)+Res | 3 raw partial (split-K)
// BM=BN=128, BK=32, 512 threads, warp grid 4x4 (32x32 per warp).
// smem: Ah/Al/Wh/Wl each [128][36] floats -> 73728 B total.
#define LDS_STRIDE 36
#define TG_SMEM (4*128*LDS_STRIDE*4)
template<int EPI>
__global__ void __launch_bounds__(512)
tgemm_tf32(const float* __restrict__ A, long lda,
           const float* __restrict__ W, long ldw,
           const float* __restrict__ bias, const float* __restrict__ Res,
           float* __restrict__ C, long ldc, int Kloc, long partStride)
{
    extern __shared__ float smf[];
    float* Ah = smf;
    float* Al = smf + 128*LDS_STRIDE;
    float* Wh = smf + 2*128*LDS_STRIDE;
    float* Wl = smf + 3*128*LDS_STRIDE;

    const int tid = threadIdx.x;
    const int wid = tid >> 5;
    const int lane = tid & 31;
    const int g   = lane >> 2;      // groupID 0..7
    const int tig = lane & 3;       // thread-in-group 0..3
    const int wm = (wid & 3) * 32;  // warp m offset within block tile
    const int wn = (wid >> 2) * 32; // warp n offset

    const int m0 = blockIdx.y * 128;
    const int n0 = blockIdx.x * 128;
    const long kbase = (long)blockIdx.z * Kloc;
    float* Cp = C + (EPI == 3 ? (long)blockIdx.z * partStride : 0);
    const bool wal = ((ldw & 3) == 0);
    const int KT = Kloc / 32;

    float acc[2][4][4];
#pragma unroll
    for (int mt = 0; mt < 2; mt++)
#pragma unroll
        for (int nt = 0; nt < 4; nt++)
#pragma unroll
            for (int r = 0; r < 4; r++) acc[mt][nt][r] = 0.f;

    float4 fa[2], fw[2];

    auto loadFrag = [&](int kt) {
        const long kk = kbase + (long)kt * 32;
#pragma unroll
        for (int i = 0; i < 2; i++) {
            int v = tid + i * 512; int row = v >> 3, q = v & 7;
            fa[i] = *reinterpret_cast<const float4*>(A + (size_t)(m0 + row) * lda + kk + q * 4);
            const float* pw = W + (size_t)(n0 + row) * ldw + kk + q * 4;
            if (wal) fw[i] = *reinterpret_cast<const float4*>(pw);
            else     fw[i] = make_float4(pw[0], pw[1], pw[2], pw[3]);
        }
    };
    auto storeFrag = [&]() {
#pragma unroll
        for (int i = 0; i < 2; i++) {
            int v = tid + i * 512; int row = v >> 3, q = v & 7;
            int off = row * LDS_STRIDE + q * 4;
            splitStore(fa[i], Ah, Al, off);
            splitStore(fw[i], Wh, Wl, off);
        }
    };
    auto compute = [&]() {
#pragma unroll
        for (int ks = 0; ks < 4; ks++) {
            const int k0 = ks * 8;
            uint32_t ah[2][4], al[2][4];
#pragma unroll
            for (int mt = 0; mt < 2; mt++) {
                int r = wm + mt * 16;
                ah[mt][0] = __float_as_uint(Ah[(r+g)*LDS_STRIDE + k0 + tig]);
                ah[mt][1] = __float_as_uint(Ah[(r+g+8)*LDS_STRIDE + k0 + tig]);
                ah[mt][2] = __float_as_uint(Ah[(r+g)*LDS_STRIDE + k0 + tig + 4]);
                ah[mt][3] = __float_as_uint(Ah[(r+g+8)*LDS_STRIDE + k0 + tig + 4]);
                al[mt][0] = __float_as_uint(Al[(r+g)*LDS_STRIDE + k0 + tig]);
                al[mt][1] = __float_as_uint(Al[(r+g+8)*LDS_STRIDE + k0 + tig]);
                al[mt][2] = __float_as_uint(Al[(r+g)*LDS_STRIDE + k0 + tig + 4]);
                al[mt][3] = __float_as_uint(Al[(r+g+8)*LDS_STRIDE + k0 + tig + 4]);
            }
            uint32_t bh[4][2], bl[4][2];
#pragma unroll
            for (int nt = 0; nt < 4; nt++) {
                int c = wn + nt * 8;
                bh[nt][0] = __float_as_uint(Wh[(c+g)*LDS_STRIDE + k0 + tig]);
                bh[nt][1] = __float_as_uint(Wh[(c+g)*LDS_STRIDE + k0 + tig + 4]);
                bl[nt][0] = __float_as_uint(Wl[(c+g)*LDS_STRIDE + k0 + tig]);
                bl[nt][1] = __float_as_uint(Wl[(c+g)*LDS_STRIDE + k0 + tig + 4]);
            }
#pragma unroll
            for (int mt = 0; mt < 2; mt++)
#pragma unroll
                for (int nt = 0; nt < 4; nt++) {
                    MMA_TF32(acc[mt][nt], al[mt], bh[nt]);  // lo*hi
                    MMA_TF32(acc[mt][nt], ah[mt], bl[nt]);  // hi*lo
                    MMA_TF32(acc[mt][nt], ah[mt], bh[nt]);  // hi*hi
                }
        }
    };

    // prologue
    loadFrag(0);
    storeFrag();
    __syncthreads();

    for (int kt = 0; kt < KT; kt++) {
        if (kt + 1 < KT) loadFrag(kt + 1);   // prefetch gmem into regs
        compute();
        __syncthreads();
        if (kt + 1 < KT) { storeFrag(); __syncthreads(); }
    }

    // epilogue: c0/c1 -> (row g, cols 2tig,2tig+1); c2/c3 -> row g+8
#pragma unroll
    for (int mt = 0; mt < 2; mt++) {
#pragma unroll
        for (int nt = 0; nt < 4; nt++) {
            const int col = n0 + wn + nt * 8 + 2 * tig;
            float2 b2 = make_float2(0.f, 0.f);
            if (EPI != 3) b2 = *reinterpret_cast<const float2*>(bias + col);
#pragma unroll
            for (int half = 0; half < 2; half++) {
                const int row = m0 + wm + mt * 16 + g + half * 8;
                float vx = acc[mt][nt][2*half + 0] + b2.x;
                float vy = acc[mt][nt][2*half + 1] + b2.y;
                if (EPI == 1 || EPI == 2) { vx = fmaxf(vx, 0.f); vy = fmaxf(vy, 0.f); }
                if (EPI == 2) {
                    float2 r2 = *reinterpret_cast<const float2*>(Res + (size_t)row * ldc + col);
                    vx += r2.x; vy += r2.y;
                }
                *reinterpret_cast<float2*>(Cp + (size_t)row * ldc + col) = make_float2(vx, vy);
            }
        }
    }
}

// ============== fc1 split-K reduce + bias + last_action tail + relu ==============
__global__ void red_fc1(const float* __restrict__ part, const float* __restrict__ la,
                        const float* __restrict__ w1, const float* __restrict__ b1,
                        float* __restrict__ t1)
{
    const int m = blockIdx.y;
    const int n = blockIdx.x * 256 + threadIdx.x;
    __shared__ float las[AA];
    if (threadIdx.x < AA) las[threadIdx.x] = la[m * AA + threadIdx.x];
    __syncthreads();
    float s = b1[n];
#pragma unroll
    for (int z = 0; z < FC1_SPLITS; z++)
        s += part[(size_t)z * (BB * HH) + (size_t)m * HH + n];
    const float* w = w1 + (size_t)n * LDW1 + KFLAT;
    float acc = 0.f;
    for (int j = 0; j < AA; j++) acc += las[j] * w[j];
    t1[(size_t)m * HH + n] = fmaxf(s + acc, 0.f);
}

// ================= fp32 fallback GEMM (fc5 only, N=129 ragged) =================
template<int BM, int BN, int BK, int TM, int TN>
__global__ void __launch_bounds__((BM/TM)*(BN/TN))
gemm_tn(const float* __restrict__ A, int lda,
        const float* __restrict__ W, int ldw,
        const float* __restrict__ bias,
        float* __restrict__ C, int M, int N, int K)
{
    constexpr int THREADS = (BM/TM)*(BN/TN);
    constexpr int KV = BK / 4;
    __shared__ __align__(16) float As[BK][BM];
    __shared__ __align__(16) float Ws[BK][BN];
    const int tid = threadIdx.x;
    const int m0 = blockIdx.y * BM;
    const int n0 = blockIdx.x * BN;
    const int tnx = tid % (BN/TN);
    const int tmy = tid / (BN/TN);
    float acc[TM][TN];
#pragma unroll
    for (int i = 0; i < TM; i++)
#pragma unroll
        for (int j = 0; j < TN; j++) acc[i][j] = 0.f;
    for (int k0 = 0; k0 < K; k0 += BK) {
#pragma unroll
        for (int it = 0; it < (BM*KV)/THREADS; it++) {
            int v = tid + it * THREADS; int row = v / KV, kq = v % KV;
            float4 f = make_float4(0.f,0.f,0.f,0.f);
            if (m0 + row < M) f = *reinterpret_cast<const float4*>(A + (size_t)(m0+row)*lda + k0 + kq*4);
            As[kq*4+0][row]=f.x; As[kq*4+1][row]=f.y; As[kq*4+2][row]=f.z; As[kq*4+3][row]=f.w;
        }
#pragma unroll
        for (int it = 0; it < (BN*KV)/THREADS; it++) {
            int v = tid + it * THREADS; int row = v / KV, kq = v % KV;
            float4 f = make_float4(0.f,0.f,0.f,0.f);
            if (n0 + row < N) f = *reinterpret_cast<const float4*>(W + (size_t)(n0+row)*ldw + k0 + kq*4);
            Ws[kq*4+0][row]=f.x; Ws[kq*4+1][row]=f.y; Ws[kq*4+2][row]=f.z; Ws[kq*4+3][row]=f.w;
        }
        __syncthreads();
#pragma unroll
        for (int kk = 0; kk < BK; kk++) {
            float a[TM], w[TN];
#pragma unroll
            for (int i = 0; i < TM; i++) a[i] = As[kk][tmy*TM + i];
#pragma unroll
            for (int j = 0; j < TN; j++) w[j] = Ws[kk][tnx*TN + j];
#pragma unroll
            for (int i = 0; i < TM; i++)
#pragma unroll
                for (int j = 0; j < TN; j++) acc[i][j] += a[i] * w[j];
        }
        __syncthreads();
    }
#pragma unroll
    for (int i = 0; i < TM; i++) {
        int m = m0 + tmy*TM + i; if (m >= M) continue;
#pragma unroll
        for (int j = 0; j < TN; j++) {
            int n = n0 + tnx*TN + j; if (n >= N) continue;
            C[(size_t)m * N + n] = acc[i][j] + bias[n];
        }
    }
}

// ================= attention: one block per (batch, head) =================
#define ATTN_SMEM ((3*128*65 + 128*129)*4)
__global__ void __launch_bounds__(128)
attn_kernel(const float* __restrict__ qkv, float* __restrict__ ctx)
{
    const int b = blockIdx.x / NH;
    const int h = blockIdx.x % NH;
    extern __shared__ float sm[];
    float* qs = sm;
    float* ks = sm + 128*65;
    float* vs = sm + 2*128*65;
    float* sc = sm + 3*128*65;
    const int tid = threadIdx.x;

    const size_t base = (size_t)b * SS * (3*EE) + (size_t)h * HD;
    for (int idx = tid; idx < SS*HD; idx += 128) {
        int s = idx >> 6, d = idx & 63;
        const float* p = qkv + base + (size_t)s * (3*EE);
        qs[s*65 + d] = p[d] * 0.125f;
        ks[s*65 + d] = p[EE + d];
        vs[s*65 + d] = p[2*EE + d];
    }
    __syncthreads();

    float qreg[HD];
#pragma unroll
    for (int d = 0; d < HD; d++) qreg[d] = qs[tid*65 + d];

    float mx = -1e30f;
    for (int j = 0; j < SS; j++) {
        float s = 0.f;
#pragma unroll
        for (int d = 0; d < HD; d++) s += qreg[d] * ks[j*65 + d];
        sc[tid*129 + j] = s;
        mx = fmaxf(mx, s);
    }
    float sum = 0.f;
    for (int j = 0; j < SS; j++) {
        float e = expf(sc[tid*129 + j] - mx);
        sc[tid*129 + j] = e;
        sum += e;
    }
    const float inv = 1.f / sum;
    float acc[HD];
#pragma unroll
    for (int d = 0; d < HD; d++) acc[d] = 0.f;
    for (int j = 0; j < SS; j++) {
        float w = sc[tid*129 + j] * inv;
#pragma unroll
        for (int d = 0; d < HD; d++) acc[d] += w * vs[j*65 + d];
    }
    float* outp = ctx + ((size_t)b * SS + tid) * EE + h * HD;
#pragma unroll
    for (int d = 0; d < HD; d++) outp[d] = acc[d];
}

// ================= block reduce / layernorm =================
__device__ __forceinline__ float block_reduce_sum(float v)
{
    __shared__ float shm[32];
    int lane = threadIdx.x & 31, wid = threadIdx.x >> 5;
#pragma unroll
    for (int o = 16; o > 0; o >>= 1) v += __shfl_down_sync(0xffffffffu, v, o);
    if (lane == 0) shm[wid] = v;
    __syncthreads();
    float r = (threadIdx.x < (blockDim.x >> 5)) ? shm[threadIdx.x] : 0.f;
    if (wid == 0) {
#pragma unroll
        for (int o = 16; o > 0; o >>= 1) r += __shfl_down_sync(0xffffffffu, r, o);
        if (lane == 0) shm[0] = r;
    }
    __syncthreads();
    r = shm[0];
    __syncthreads();
    return r;
}

template<bool ADD>
__global__ void ln_kernel(const float* __restrict__ X, const float* __restrict__ Y,
                          const float* __restrict__ g, const float* __restrict__ be,
                          float* __restrict__ out, int D)
{
    const size_t row = blockIdx.x;
    const float* x = X + row * D;
    const float* y = ADD ? (Y + row * D) : nullptr;
    float s = 0.f, s2 = 0.f;
    for (int i = threadIdx.x; i < D; i += blockDim.x) {
        float v = x[i];
        if (ADD) v += y[i];
        s += v; s2 += v * v;
    }
    float S  = block_reduce_sum(s);
    float S2 = block_reduce_sum(s2);
    float mean = S / (float)D;
    float var  = S2 / (float)D - mean * mean;
    float inv  = rsqrtf(var + 1e-5f);
    for (int i = threadIdx.x; i < D; i += blockDim.x) {
        float v = x[i];
        if (ADD) v += y[i];
        out[row * D + i] = (v - mean) * inv * g[i] + be[i];
    }
}

// ================= fc6 + top-K + masked softmax =================
__global__ void head_kernel(const float* __restrict__ t5, const float* __restrict__ la,
                            const float* __restrict__ w6, const float* __restrict__ b6,
                            float* __restrict__ out)
{
    const int b = blockIdx.x;
    __shared__ float cat[2*AA];
    __shared__ float sc[AA];
    __shared__ float red[256];
    const int tid = threadIdx.x;

    for (int i = tid; i < 2*AA; i += 256)
        cat[i] = (i < AA) ? t5[b*AA + i] : la[b*AA + (i - AA)];
    __syncthreads();

    if (tid < AA) {
        float a = b6[tid];
        const float* w = w6 + tid * (2*AA);
        for (int j = 0; j < 2*AA; j++) a += w[j] * cat[j];
        sc[tid] = a;
    }
    __syncthreads();

    bool winner = false; float v = 0.f;
    if (tid < AA) {
        v = sc[tid];
        int cnt = 0;
        for (int j = 0; j < AA; j++) {
            float u = sc[j];
            cnt += (u > v) || (u == v && j < tid);
        }
        winner = cnt < KWIN;
    }
    red[tid] = (tid < AA && winner) ? v : -1e30f;
    __syncthreads();
    for (int s = 128; s > 0; s >>= 1) {
        if (tid < s) red[tid] = fmaxf(red[tid], red[tid + s]);
        __syncthreads();
    }
    float mx = red[0];
    __syncthreads();
    float e = (tid < AA && winner) ? expf(v - mx) : 0.f;
    red[tid] = e;
    __syncthreads();
    for (int s = 128; s > 0; s >>= 1) {
        if (tid < s) red[tid] += red[tid + s];
        __syncthreads();
    }
    float inv = 1.f / red[0];
    if (tid < AA) out[b*AA + tid] = e * inv;
}

// ================= launcher =================
extern "C" void kernel_launch(void* const* d_in, const int* in_sizes, int n_in,
                              void* d_out, int out_size)
{
    const float* hist      = (const float*)d_in[0];
    const float* la        = (const float*)d_in[1];
    const float* embed_w   = (const float*)d_in[2];
    const float* embed_b   = (const float*)d_in[3];
    const float* in_proj_w = (const float*)d_in[4];
    const float* in_proj_b = (const float*)d_in[5];
    const float* out_proj_w= (const float*)d_in[6];
    const float* out_proj_b= (const float*)d_in[7];
    const float* lnorm_g   = (const float*)d_in[8];
    const float* lnorm_b   = (const float*)d_in[9];
    const float* fc1_w     = (const float*)d_in[10];
    const float* fc1_b     = (const float*)d_in[11];
    const float* fc2_w     = (const float*)d_in[12];
    const float* fc2_b     = (const float*)d_in[13];
    const float* ln1_g     = (const float*)d_in[14];
    const float* ln1_b     = (const float*)d_in[15];
    const float* fc3_w     = (const float*)d_in[16];
    const float* fc3_b     = (const float*)d_in[17];
    const float* fc4_w     = (const float*)d_in[18];
    const float* fc4_b     = (const float*)d_in[19];
    const float* fc5_w     = (const float*)d_in[20];
    const float* fc5_b     = (const float*)d_in[21];
    const float* fc6_w     = (const float*)d_in[22];
    const float* fc6_b     = (const float*)d_in[23];
    float* out = (float*)d_out;

    float *h, *qkv, *ctx, *t1, *t2, *t3, *t4, *t5;
    cudaGetSymbolAddress((void**)&h,   g_h);
    cudaGetSymbolAddress((void**)&qkv, g_qkv);
    cudaGetSymbolAddress((void**)&ctx, g_ctx);
    cudaGetSymbolAddress((void**)&t1,  g_t1);
    cudaGetSymbolAddress((void**)&t2,  g_t2);
    cudaGetSymbolAddress((void**)&t3,  g_t3);
    cudaGetSymbolAddress((void**)&t4,  g_t4);
    cudaGetSymbolAddress((void**)&t5,  g_t5);

    cudaFuncSetAttribute(tgemm_tf32<0>, cudaFuncAttributeMaxDynamicSharedMemorySize, TG_SMEM);
    cudaFuncSetAttribute(tgemm_tf32<1>, cudaFuncAttributeMaxDynamicSharedMemorySize, TG_SMEM);
    cudaFuncSetAttribute(tgemm_tf32<2>, cudaFuncAttributeMaxDynamicSharedMemorySize, TG_SMEM);
    cudaFuncSetAttribute(tgemm_tf32<3>, cudaFuncAttributeMaxDynamicSharedMemorySize, TG_SMEM);
    cudaFuncSetAttribute(attn_kernel,   cudaFuncAttributeMaxDynamicSharedMemorySize, ATTN_SMEM);

    // 1) embed: h = hist @ embed_w^T + b          [65536,640]
    tgemm_tf32<0><<<dim3(EE/128, BS/128, 1), 512, TG_SMEM>>>(
        hist, EE, embed_w, EE, embed_b, nullptr, h, EE, EE, 0);

    // 2) qkv = h @ in_proj_w^T + b                [65536,1920]
    tgemm_tf32<0><<<dim3((3*EE)/128, BS/128, 1), 512, TG_SMEM>>>(
        h, EE, in_proj_w, EE, in_proj_b, nullptr, qkv, 3*EE, EE, 0);

    // 3) attention -> ctx
    attn_kernel<<<BB*NH, 128, ATTN_SMEM>>>(qkv, ctx);

    // 4) attn_out = ctx @ out_proj_w^T + b  (into qkv buffer)
    tgemm_tf32<0><<<dim3(EE/128, BS/128, 1), 512, TG_SMEM>>>(
        ctx, EE, out_proj_w, EE, out_proj_b, nullptr, qkv, EE, EE, 0);

    // 5) x = LN(attn_out + h) -> x_flat (ctx buffer)
    ln_kernel<true><<<BS, 256>>>(qkv, h, lnorm_g, lnorm_b, ctx, EE);

    // 6) fc1 split-K over 81920 aligned cols -> partials in g_h
    tgemm_tf32<3><<<dim3(HH/128, BB/128, FC1_SPLITS), 512, TG_SMEM>>>(
        ctx, KFLAT, fc1_w, LDW1, nullptr, nullptr, h, HH, FC1_KLOC, (long)BB*HH);

    // 7) reduce partials + bias + last_action tail + relu -> t1
    red_fc1<<<dim3(HH/256, BB), 256>>>(h, la, fc1_w, fc1_b, t1);

    // 8) fc2: t2 = relu(t1 @ fc2^T + b) + t1
    tgemm_tf32<2><<<dim3(HH/128, BB/128, 1), 512, TG_SMEM>>>(
        t1, HH, fc2_w, HH, fc2_b, t1, t2, HH, HH, 0);

    // 9) ln1 in-place on t2
    ln_kernel<false><<<BB, 256>>>(t2, nullptr, ln1_g, ln1_b, t2, HH);

    // 10) fc3 relu                                 [512,1024]
    tgemm_tf32<1><<<dim3((HH/2)/128, BB/128, 1), 512, TG_SMEM>>>(
        t2, HH, fc3_w, HH, fc3_b, nullptr, t3, HH/2, HH, 0);

    // 11) fc4 relu                                 [512,512]
    tgemm_tf32<1><<<dim3((HH/4)/128, BB/128, 1), 512, TG_SMEM>>>(
        t3, HH/2, fc4_w, HH/2, fc4_b, nullptr, t4, HH/4, HH/2, 0);

    // 12) fc5 (N=129 ragged -> fp32 path)          [512,129]
    gemm_tn<64,64,16,4,4><<<dim3((AA+63)/64, BB/64), 256>>>(
        t4, HH/4, fc5_w, HH/4, fc5_b, t5, BB, AA, HH/4);

    // 13) fc6 + top-K + masked softmax -> out      [512,129]
    head_kernel<<<BB, 256>>>(t5, la, fc6_w, fc6_b, out);
}

// round 6
// speedup vs baseline: 1.8508x; 1.1502x over previous
#include <cuda_runtime.h>
#include <cstdint>
#include <math.h>

// ---------------- problem constants ----------------
#define BB   512
#define SS   128
#define EE   640
#define AA   129
#define HH   2048
#define NH   10
#define HD   64
#define KWIN 64
#define BS   (BB*SS)          // 65536
#define KFLAT (EE*SS)         // 81920
#define LDW1 (KFLAT + AA)     // 82049
#define FC1_SPLITS 8
#define FC1_KLOC   (KFLAT/FC1_SPLITS)   // 10240

// ---------------- scratch (device globals, no allocs) ----------------
__device__ float g_h[BS * EE];          // h; later fc1 split-K partials
__device__ float g_qkv[BS * 3 * EE];    // qkv; attn_out; later fc2/3/4 partials
__device__ float g_ctx[BS * EE];        // ctx; x_flat
__device__ float g_t1[BB * HH];
__device__ float g_t2[BB * HH];
__device__ float g_t3[BB * (HH/2)];
__device__ float g_t4[BB * (HH/4)];
__device__ float g_t5[BB * AA];

// ================= helpers =================
__device__ __forceinline__ uint32_t f2tf32(float x) {
    uint32_t r; asm("cvt.rna.tf32.f32 %0, %1;" : "=r"(r) : "f"(x)); return r;
}
#define MMA_TF32(c, a, b) \
    asm volatile("mma.sync.aligned.m16n8k8.row.col.f32.tf32.tf32.f32 " \
        "{%0,%1,%2,%3}, {%4,%5,%6,%7}, {%8,%9}, {%0,%1,%2,%3};" \
        : "+f"((c)[0]), "+f"((c)[1]), "+f"((c)[2]), "+f"((c)[3]) \
        : "r"((a)[0]), "r"((a)[1]), "r"((a)[2]), "r"((a)[3]), \
          "r"((b)[0]), "r"((b)[1]))

// split fp32 -> (hi,lo) tf32 and store to smem (16B vectors)
__device__ __forceinline__ void splitStore(float4 f, float* hi, float* lo, int off) {
    float h0 = __uint_as_float(f2tf32(f.x));
    float h1 = __uint_as_float(f2tf32(f.y));
    float h2 = __uint_as_float(f2tf32(f.z));
    float h3 = __uint_as_float(f2tf32(f.w));
    float4 hv = make_float4(h0, h1, h2, h3);
    float4 lv = make_float4(
        __uint_as_float(f2tf32(f.x - h0)),
        __uint_as_float(f2tf32(f.y - h1)),
        __uint_as_float(f2tf32(f.z - h2)),
        __uint_as_float(f2tf32(f.w - h3)));
    *reinterpret_cast<float4*>(hi + off) = hv;
    *reinterpret_cast<float4*>(lo + off) = lv;
}

// ============== 3xTF32 mma.sync GEMM:  C = A(M,K) @ W(N,K)^T ==============
// EPI: 0 bias | 1 bias+relu | 2 relu(bias+)+Res | 3 raw partial (split-K)
// BM=BN=128, BK=32, 512 threads, warp grid 4x4 (32x32 per warp).
// smem double-buffered: 2 x (Ah/Al/Wh/Wl each [128][36]) = 147456 B.
#define LDS_STRIDE 36
#define BUF_FLOATS (4*128*LDS_STRIDE)
#define TG_SMEM (2*BUF_FLOATS*4)
template<int EPI>
__global__ void __launch_bounds__(512)
tgemm_tf32(const float* __restrict__ A, long lda,
           const float* __restrict__ W, long ldw,
           const float* __restrict__ bias, const float* __restrict__ Res,
           float* __restrict__ C, long ldc, int Kloc, long partStride)
{
    extern __shared__ float smf[];

    const int tid = threadIdx.x;
    const int wid = tid >> 5;
    const int lane = tid & 31;
    const int g   = lane >> 2;      // groupID 0..7
    const int tig = lane & 3;       // thread-in-group 0..3
    const int wm = (wid & 3) * 32;  // warp m offset
    const int wn = (wid >> 2) * 32; // warp n offset

    const int m0 = blockIdx.y * 128;
    const int n0 = blockIdx.x * 128;
    const long kbase = (long)blockIdx.z * Kloc;
    float* Cp = C + (EPI == 3 ? (long)blockIdx.z * partStride : 0);
    const bool wal = ((ldw & 3) == 0);
    const int KT = Kloc / 32;

    float acc[2][4][4];
#pragma unroll
    for (int mt = 0; mt < 2; mt++)
#pragma unroll
        for (int nt = 0; nt < 4; nt++)
#pragma unroll
            for (int r = 0; r < 4; r++) acc[mt][nt][r] = 0.f;

    float4 fa[2], fw[2];

    auto loadFrag = [&](int kt) {
        const long kk = kbase + (long)kt * 32;
#pragma unroll
        for (int i = 0; i < 2; i++) {
            int v = tid + i * 512; int row = v >> 3, q = v & 7;
            fa[i] = *reinterpret_cast<const float4*>(A + (size_t)(m0 + row) * lda + kk + q * 4);
            const float* pw = W + (size_t)(n0 + row) * ldw + kk + q * 4;
            if (wal) fw[i] = *reinterpret_cast<const float4*>(pw);
            else     fw[i] = make_float4(pw[0], pw[1], pw[2], pw[3]);
        }
    };
    auto storeFrag = [&](int sbi) {
        float* Ah = smf + sbi * BUF_FLOATS;
        float* Al = Ah + 128*LDS_STRIDE;
        float* Wh = Ah + 2*128*LDS_STRIDE;
        float* Wl = Ah + 3*128*LDS_STRIDE;
#pragma unroll
        for (int i = 0; i < 2; i++) {
            int v = tid + i * 512; int row = v >> 3, q = v & 7;
            int off = row * LDS_STRIDE + q * 4;
            splitStore(fa[i], Ah, Al, off);
            splitStore(fw[i], Wh, Wl, off);
        }
    };
    auto compute = [&](int sbi) {
        float* Ah = smf + sbi * BUF_FLOATS;
        float* Al = Ah + 128*LDS_STRIDE;
        float* Wh = Ah + 2*128*LDS_STRIDE;
        float* Wl = Ah + 3*128*LDS_STRIDE;
#pragma unroll
        for (int ks = 0; ks < 4; ks++) {
            const int k0 = ks * 8;
            uint32_t ah[2][4], al[2][4];
#pragma unroll
            for (int mt = 0; mt < 2; mt++) {
                int r = wm + mt * 16;
                ah[mt][0] = __float_as_uint(Ah[(r+g)*LDS_STRIDE + k0 + tig]);
                ah[mt][1] = __float_as_uint(Ah[(r+g+8)*LDS_STRIDE + k0 + tig]);
                ah[mt][2] = __float_as_uint(Ah[(r+g)*LDS_STRIDE + k0 + tig + 4]);
                ah[mt][3] = __float_as_uint(Ah[(r+g+8)*LDS_STRIDE + k0 + tig + 4]);
                al[mt][0] = __float_as_uint(Al[(r+g)*LDS_STRIDE + k0 + tig]);
                al[mt][1] = __float_as_uint(Al[(r+g+8)*LDS_STRIDE + k0 + tig]);
                al[mt][2] = __float_as_uint(Al[(r+g)*LDS_STRIDE + k0 + tig + 4]);
                al[mt][3] = __float_as_uint(Al[(r+g+8)*LDS_STRIDE + k0 + tig + 4]);
            }
            uint32_t bh[4][2], bl[4][2];
#pragma unroll
            for (int nt = 0; nt < 4; nt++) {
                int c = wn + nt * 8;
                bh[nt][0] = __float_as_uint(Wh[(c+g)*LDS_STRIDE + k0 + tig]);
                bh[nt][1] = __float_as_uint(Wh[(c+g)*LDS_STRIDE + k0 + tig + 4]);
                bl[nt][0] = __float_as_uint(Wl[(c+g)*LDS_STRIDE + k0 + tig]);
                bl[nt][1] = __float_as_uint(Wl[(c+g)*LDS_STRIDE + k0 + tig + 4]);
            }
#pragma unroll
            for (int mt = 0; mt < 2; mt++)
#pragma unroll
                for (int nt = 0; nt < 4; nt++) {
                    MMA_TF32(acc[mt][nt], al[mt], bh[nt]);  // lo*hi
                    MMA_TF32(acc[mt][nt], ah[mt], bl[nt]);  // hi*lo
                    MMA_TF32(acc[mt][nt], ah[mt], bh[nt]);  // hi*hi
                }
        }
    };

    // prologue: tile0 -> buf0; tile1 in regs
    loadFrag(0);
    storeFrag(0);
    if (KT > 1) loadFrag(1);
    __syncthreads();

    for (int kt = 0; kt < KT; kt++) {
        if (kt + 1 < KT) storeFrag((kt + 1) & 1);  // STS overlaps MMAs below
        if (kt + 2 < KT) loadFrag(kt + 2);          // LDG prefetch
        compute(kt & 1);
        __syncthreads();
    }

    // epilogue
#pragma unroll
    for (int mt = 0; mt < 2; mt++) {
#pragma unroll
        for (int nt = 0; nt < 4; nt++) {
            const int col = n0 + wn + nt * 8 + 2 * tig;
            float2 b2 = make_float2(0.f, 0.f);
            if (EPI != 3) b2 = *reinterpret_cast<const float2*>(bias + col);
#pragma unroll
            for (int half = 0; half < 2; half++) {
                const int row = m0 + wm + mt * 16 + g + half * 8;
                float vx = acc[mt][nt][2*half + 0] + b2.x;
                float vy = acc[mt][nt][2*half + 1] + b2.y;
                if (EPI == 1 || EPI == 2) { vx = fmaxf(vx, 0.f); vy = fmaxf(vy, 0.f); }
                if (EPI == 2) {
                    float2 r2 = *reinterpret_cast<const float2*>(Res + (size_t)row * ldc + col);
                    vx += r2.x; vy += r2.y;
                }
                *reinterpret_cast<float2*>(Cp + (size_t)row * ldc + col) = make_float2(vx, vy);
            }
        }
    }
}

// ============== generic split-K reduce: bias [+relu] [+res] ==============
// EPI: 1 = relu(sum+bias), 2 = relu(sum+bias) + Res
template<int NSPLIT, int EPI>
__global__ void red_epi(const float* __restrict__ part, long stride,
                        const float* __restrict__ bias, const float* __restrict__ Res,
                        float* __restrict__ out, int N)
{
    const int m = blockIdx.y;
    const int n = blockIdx.x * 256 + threadIdx.x;
    float s = bias[n];
#pragma unroll
    for (int z = 0; z < NSPLIT; z++)
        s += part[(size_t)z * stride + (size_t)m * N + n];
    s = fmaxf(s, 0.f);
    if (EPI == 2) s += Res[(size_t)m * N + n];
    out[(size_t)m * N + n] = s;
}

// ============== fc1 split-K reduce + bias + last_action tail + relu ==============
__global__ void red_fc1(const float* __restrict__ part, const float* __restrict__ la,
                        const float* __restrict__ w1, const float* __restrict__ b1,
                        float* __restrict__ t1)
{
    const int m = blockIdx.y;
    const int n = blockIdx.x * 256 + threadIdx.x;
    __shared__ float las[AA];
    if (threadIdx.x < AA) las[threadIdx.x] = la[m * AA + threadIdx.x];
    __syncthreads();
    float s = b1[n];
#pragma unroll
    for (int z = 0; z < FC1_SPLITS; z++)
        s += part[(size_t)z * (BB * HH) + (size_t)m * HH + n];
    const float* w = w1 + (size_t)n * LDW1 + KFLAT;
    float acc = 0.f;
    for (int j = 0; j < AA; j++) acc += las[j] * w[j];
    t1[(size_t)m * HH + n] = fmaxf(s + acc, 0.f);
}

// ================= fp32 fallback GEMM (fc5 only, N=129 ragged) =================
template<int BM, int BN, int BK, int TM, int TN>
__global__ void __launch_bounds__((BM/TM)*(BN/TN))
gemm_tn(const float* __restrict__ A, int lda,
        const float* __restrict__ W, int ldw,
        const float* __restrict__ bias,
        float* __restrict__ C, int M, int N, int K)
{
    constexpr int THREADS = (BM/TM)*(BN/TN);
    constexpr int KV = BK / 4;
    __shared__ __align__(16) float As[BK][BM];
    __shared__ __align__(16) float Ws[BK][BN];
    const int tid = threadIdx.x;
    const int m0 = blockIdx.y * BM;
    const int n0 = blockIdx.x * BN;
    const int tnx = tid % (BN/TN);
    const int tmy = tid / (BN/TN);
    float acc[TM][TN];
#pragma unroll
    for (int i = 0; i < TM; i++)
#pragma unroll
        for (int j = 0; j < TN; j++) acc[i][j] = 0.f;
    for (int k0 = 0; k0 < K; k0 += BK) {
#pragma unroll
        for (int it = 0; it < (BM*KV)/THREADS; it++) {
            int v = tid + it * THREADS; int row = v / KV, kq = v % KV;
            float4 f = make_float4(0.f,0.f,0.f,0.f);
            if (m0 + row < M) f = *reinterpret_cast<const float4*>(A + (size_t)(m0+row)*lda + k0 + kq*4);
            As[kq*4+0][row]=f.x; As[kq*4+1][row]=f.y; As[kq*4+2][row]=f.z; As[kq*4+3][row]=f.w;
        }
#pragma unroll
        for (int it = 0; it < (BN*KV)/THREADS; it++) {
            int v = tid + it * THREADS; int row = v / KV, kq = v % KV;
            float4 f = make_float4(0.f,0.f,0.f,0.f);
            if (n0 + row < N) f = *reinterpret_cast<const float4*>(W + (size_t)(n0+row)*ldw + k0 + kq*4);
            Ws[kq*4+0][row]=f.x; Ws[kq*4+1][row]=f.y; Ws[kq*4+2][row]=f.z; Ws[kq*4+3][row]=f.w;
        }
        __syncthreads();
#pragma unroll
        for (int kk = 0; kk < BK; kk++) {
            float a[TM], w[TN];
#pragma unroll
            for (int i = 0; i < TM; i++) a[i] = As[kk][tmy*TM + i];
#pragma unroll
            for (int j = 0; j < TN; j++) w[j] = Ws[kk][tnx*TN + j];
#pragma unroll
            for (int i = 0; i < TM; i++)
#pragma unroll
                for (int j = 0; j < TN; j++) acc[i][j] += a[i] * w[j];
        }
        __syncthreads();
    }
#pragma unroll
    for (int i = 0; i < TM; i++) {
        int m = m0 + tmy*TM + i; if (m >= M) continue;
#pragma unroll
        for (int j = 0; j < TN; j++) {
            int n = n0 + tnx*TN + j; if (n >= N) continue;
            C[(size_t)m * N + n] = acc[i][j] + bias[n];
        }
    }
}

// ================= attention: one block per (batch, head), float4 ILP =================
#define ATTN_SMEM ((2*128*64 + 128*129)*4)
__global__ void __launch_bounds__(128)
attn_kernel(const float* __restrict__ qkv, float* __restrict__ ctx)
{
    const int b = blockIdx.x / NH;
    const int h = blockIdx.x % NH;
    extern __shared__ float sm[];
    float* ks = sm;                  // [128][64]
    float* vs = sm + 128*64;         // [128][64]
    float* sc = sm + 2*128*64;       // [128][129]
    const int tid = threadIdx.x;     // 128

    const size_t base = (size_t)b * SS * (3*EE) + (size_t)h * HD;
    for (int idx = tid; idx < SS*HD; idx += 128) {
        int s = idx >> 6, d = idx & 63;
        const float* p = qkv + base + (size_t)s * (3*EE);
        ks[s*64 + d] = p[EE + d];
        vs[s*64 + d] = p[2*EE + d];
    }
    // q row for this thread, straight from gmem, scaled
    float4 q4[16];
    {
        const float4* qp = reinterpret_cast<const float4*>(qkv + base + (size_t)tid * (3*EE));
#pragma unroll
        for (int i = 0; i < 16; i++) {
            float4 t = qp[i];
            q4[i] = make_float4(t.x*0.125f, t.y*0.125f, t.z*0.125f, t.w*0.125f);
        }
    }
    __syncthreads();

    float mx = -1e30f;
    for (int j = 0; j < SS; j++) {
        const float4* kp = reinterpret_cast<const float4*>(ks + j*64);
        float4 s4 = make_float4(0.f, 0.f, 0.f, 0.f);
#pragma unroll
        for (int i = 0; i < 16; i++) {
            float4 kv = kp[i];
            s4.x = fmaf(q4[i].x, kv.x, s4.x);
            s4.y = fmaf(q4[i].y, kv.y, s4.y);
            s4.z = fmaf(q4[i].z, kv.z, s4.z);
            s4.w = fmaf(q4[i].w, kv.w, s4.w);
        }
        float s = (s4.x + s4.y) + (s4.z + s4.w);
        sc[tid*129 + j] = s;
        mx = fmaxf(mx, s);
    }
    float sum = 0.f;
    for (int j = 0; j < SS; j++) {
        float e = expf(sc[tid*129 + j] - mx);
        sc[tid*129 + j] = e;
        sum += e;
    }
    const float inv = 1.f / sum;

    float4 a4[16];
#pragma unroll
    for (int i = 0; i < 16; i++) a4[i] = make_float4(0.f, 0.f, 0.f, 0.f);
    for (int j = 0; j < SS; j++) {
        const float w = sc[tid*129 + j] * inv;
        const float4* vp = reinterpret_cast<const float4*>(vs + j*64);
#pragma unroll
        for (int i = 0; i < 16; i++) {
            float4 vv = vp[i];
            a4[i].x = fmaf(w, vv.x, a4[i].x);
            a4[i].y = fmaf(w, vv.y, a4[i].y);
            a4[i].z = fmaf(w, vv.z, a4[i].z);
            a4[i].w = fmaf(w, vv.w, a4[i].w);
        }
    }
    float4* outp = reinterpret_cast<float4*>(ctx + ((size_t)b * SS + tid) * EE + h * HD);
#pragma unroll
    for (int i = 0; i < 16; i++) outp[i] = a4[i];
}

// ================= block reduce / layernorm =================
__device__ __forceinline__ float block_reduce_sum(float v)
{
    __shared__ float shm[32];
    int lane = threadIdx.x & 31, wid = threadIdx.x >> 5;
#pragma unroll
    for (int o = 16; o > 0; o >>= 1) v += __shfl_down_sync(0xffffffffu, v, o);
    if (lane == 0) shm[wid] = v;
    __syncthreads();
    float r = (threadIdx.x < (blockDim.x >> 5)) ? shm[threadIdx.x] : 0.f;
    if (wid == 0) {
#pragma unroll
        for (int o = 16; o > 0; o >>= 1) r += __shfl_down_sync(0xffffffffu, r, o);
        if (lane == 0) shm[0] = r;
    }
    __syncthreads();
    r = shm[0];
    __syncthreads();
    return r;
}

template<bool ADD>
__global__ void ln_kernel(const float* __restrict__ X, const float* __restrict__ Y,
                          const float* __restrict__ g, const float* __restrict__ be,
                          float* __restrict__ out, int D)
{
    const size_t row = blockIdx.x;
    const float* x = X + row * D;
    const float* y = ADD ? (Y + row * D) : nullptr;
    float s = 0.f, s2 = 0.f;
    for (int i = threadIdx.x; i < D; i += blockDim.x) {
        float v = x[i];
        if (ADD) v += y[i];
        s += v; s2 += v * v;
    }
    float S  = block_reduce_sum(s);
    float S2 = block_reduce_sum(s2);
    float mean = S / (float)D;
    float var  = S2 / (float)D - mean * mean;
    float inv  = rsqrtf(var + 1e-5f);
    for (int i = threadIdx.x; i < D; i += blockDim.x) {
        float v = x[i];
        if (ADD) v += y[i];
        out[row * D + i] = (v - mean) * inv * g[i] + be[i];
    }
}

// ================= fc6 + top-K + masked softmax =================
__global__ void head_kernel(const float* __restrict__ t5, const float* __restrict__ la,
                            const float* __restrict__ w6, const float* __restrict__ b6,
                            float* __restrict__ out)
{
    const int b = blockIdx.x;
    __shared__ float cat[2*AA];
    __shared__ float sc[AA];
    __shared__ float red[256];
    const int tid = threadIdx.x;

    for (int i = tid; i < 2*AA; i += 256)
        cat[i] = (i < AA) ? t5[b*AA + i] : la[b*AA + (i - AA)];
    __syncthreads();

    if (tid < AA) {
        float a = b6[tid];
        const float* w = w6 + tid * (2*AA);
        for (int j = 0; j < 2*AA; j++) a += w[j] * cat[j];
        sc[tid] = a;
    }
    __syncthreads();

    bool winner = false; float v = 0.f;
    if (tid < AA) {
        v = sc[tid];
        int cnt = 0;
        for (int j = 0; j < AA; j++) {
            float u = sc[j];
            cnt += (u > v) || (u == v && j < tid);
        }
        winner = cnt < KWIN;
    }
    red[tid] = (tid < AA && winner) ? v : -1e30f;
    __syncthreads();
    for (int s = 128; s > 0; s >>= 1) {
        if (tid < s) red[tid] = fmaxf(red[tid], red[tid + s]);
        __syncthreads();
    }
    float mx = red[0];
    __syncthreads();
    float e = (tid < AA && winner) ? expf(v - mx) : 0.f;
    red[tid] = e;
    __syncthreads();
    for (int s = 128; s > 0; s >>= 1) {
        if (tid < s) red[tid] += red[tid + s];
        __syncthreads();
    }
    float inv = 1.f / red[0];
    if (tid < AA) out[b*AA + tid] = e * inv;
}

// ================= launcher =================
extern "C" void kernel_launch(void* const* d_in, const int* in_sizes, int n_in,
                              void* d_out, int out_size)
{
    const float* hist      = (const float*)d_in[0];
    const float* la        = (const float*)d_in[1];
    const float* embed_w   = (const float*)d_in[2];
    const float* embed_b   = (const float*)d_in[3];
    const float* in_proj_w = (const float*)d_in[4];
    const float* in_proj_b = (const float*)d_in[5];
    const float* out_proj_w= (const float*)d_in[6];
    const float* out_proj_b= (const float*)d_in[7];
    const float* lnorm_g   = (const float*)d_in[8];
    const float* lnorm_b   = (const float*)d_in[9];
    const float* fc1_w     = (const float*)d_in[10];
    const float* fc1_b     = (const float*)d_in[11];
    const float* fc2_w     = (const float*)d_in[12];
    const float* fc2_b     = (const float*)d_in[13];
    const float* ln1_g     = (const float*)d_in[14];
    const float* ln1_b     = (const float*)d_in[15];
    const float* fc3_w     = (const float*)d_in[16];
    const float* fc3_b     = (const float*)d_in[17];
    const float* fc4_w     = (const float*)d_in[18];
    const float* fc4_b     = (const float*)d_in[19];
    const float* fc5_w     = (const float*)d_in[20];
    const float* fc5_b     = (const float*)d_in[21];
    const float* fc6_w     = (const float*)d_in[22];
    const float* fc6_b     = (const float*)d_in[23];
    float* out = (float*)d_out;

    float *h, *qkv, *ctx, *t1, *t2, *t3, *t4, *t5;
    cudaGetSymbolAddress((void**)&h,   g_h);
    cudaGetSymbolAddress((void**)&qkv, g_qkv);
    cudaGetSymbolAddress((void**)&ctx, g_ctx);
    cudaGetSymbolAddress((void**)&t1,  g_t1);
    cudaGetSymbolAddress((void**)&t2,  g_t2);
    cudaGetSymbolAddress((void**)&t3,  g_t3);
    cudaGetSymbolAddress((void**)&t4,  g_t4);
    cudaGetSymbolAddress((void**)&t5,  g_t5);

    cudaFuncSetAttribute(tgemm_tf32<0>, cudaFuncAttributeMaxDynamicSharedMemorySize, TG_SMEM);
    cudaFuncSetAttribute(tgemm_tf32<1>, cudaFuncAttributeMaxDynamicSharedMemorySize, TG_SMEM);
    cudaFuncSetAttribute(tgemm_tf32<2>, cudaFuncAttributeMaxDynamicSharedMemorySize, TG_SMEM);
    cudaFuncSetAttribute(tgemm_tf32<3>, cudaFuncAttributeMaxDynamicSharedMemorySize, TG_SMEM);
    cudaFuncSetAttribute(attn_kernel,   cudaFuncAttributeMaxDynamicSharedMemorySize, ATTN_SMEM);

    // 1) embed: h = hist @ embed_w^T + b          [65536,640]
    tgemm_tf32<0><<<dim3(EE/128, BS/128, 1), 512, TG_SMEM>>>(
        hist, EE, embed_w, EE, embed_b, nullptr, h, EE, EE, 0);

    // 2) qkv = h @ in_proj_w^T + b                [65536,1920]
    tgemm_tf32<0><<<dim3((3*EE)/128, BS/128, 1), 512, TG_SMEM>>>(
        h, EE, in_proj_w, EE, in_proj_b, nullptr, qkv, 3*EE, EE, 0);

    // 3) attention -> ctx
    attn_kernel<<<BB*NH, 128, ATTN_SMEM>>>(qkv, ctx);

    // 4) attn_out = ctx @ out_proj_w^T + b  (into qkv buffer)
    tgemm_tf32<0><<<dim3(EE/128, BS/128, 1), 512, TG_SMEM>>>(
        ctx, EE, out_proj_w, EE, out_proj_b, nullptr, qkv, EE, EE, 0);

    // 5) x = LN(attn_out + h) -> x_flat (ctx buffer)
    ln_kernel<true><<<BS, 256>>>(qkv, h, lnorm_g, lnorm_b, ctx, EE);

    // 6) fc1 split-K over 81920 aligned cols -> partials in g_h
    tgemm_tf32<3><<<dim3(HH/128, BB/128, FC1_SPLITS), 512, TG_SMEM>>>(
        ctx, KFLAT, fc1_w, LDW1, nullptr, nullptr, h, HH, FC1_KLOC, (long)BB*HH);

    // 7) reduce partials + bias + last_action tail + relu -> t1
    red_fc1<<<dim3(HH/256, BB), 256>>>(h, la, fc1_w, fc1_b, t1);

    // 8) fc2 split-K=4 -> partials in qkv; reduce: t2 = relu(.+b) + t1
    tgemm_tf32<3><<<dim3(HH/128, BB/128, 4), 512, TG_SMEM>>>(
        t1, HH, fc2_w, HH, nullptr, nullptr, qkv, HH, HH/4, (long)BB*HH);
    red_epi<4,2><<<dim3(HH/256, BB), 256>>>(qkv, (long)BB*HH, fc2_b, t1, t2, HH);

    // 9) ln1 in-place on t2
    ln_kernel<false><<<BB, 256>>>(t2, nullptr, ln1_g, ln1_b, t2, HH);

    // 10) fc3 split-K=4: t3 = relu(t2 @ fc3^T + b)  [512,1024]
    tgemm_tf32<3><<<dim3((HH/2)/128, BB/128, 4), 512, TG_SMEM>>>(
        t2, HH, fc3_w, HH, nullptr, nullptr, qkv, HH/2, HH/4, (long)BB*(HH/2));
    red_epi<4,1><<<dim3((HH/2)/256, BB), 256>>>(qkv, (long)BB*(HH/2), fc3_b, nullptr, t3, HH/2);

    // 11) fc4 split-K=4: t4 = relu(t3 @ fc4^T + b)  [512,512]
    tgemm_tf32<3><<<dim3((HH/4)/128, BB/128, 4), 512, TG_SMEM>>>(
        t3, HH/2, fc4_w, HH/2, nullptr, nullptr, qkv, HH/4, (HH/2)/4, (long)BB*(HH/4));
    red_epi<4,1><<<dim3((HH/4)/256, BB), 256>>>(qkv, (long)BB*(HH/4), fc4_b, nullptr, t4, HH/4);

    // 12) fc5 (N=129 ragged -> fp32 path)          [512,129]
    gemm_tn<64,64,16,4,4><<<dim3((AA+63)/64, BB/64), 256>>>(
        t4, HH/4, fc5_w, HH/4, fc5_b, t5, BB, AA, HH/4);

    // 13) fc6 + top-K + masked softmax -> out      [512,129]
    head_kernel<<<BB, 256>>>(t5, la, fc6_w, fc6_b, out);
}

// round 7
// speedup vs baseline: 1.9337x; 1.0448x over previous
#include <cuda_runtime.h>
#include <cstdint>
#include <math.h>

// ---------------- problem constants ----------------
#define BB   512
#define SS   128
#define EE   640
#define AA   129
#define HH   2048
#define NH   10
#define HD   64
#define KWIN 64
#define BS   (BB*SS)          // 65536
#define KFLAT (EE*SS)         // 81920
#define LDW1 (KFLAT + AA)     // 82049
#define FC1_SPLITS 8
#define FC1_KLOC   (KFLAT/FC1_SPLITS)   // 10240

// ---------------- scratch (device globals, no allocs) ----------------
__device__ float g_h[BS * EE];          // h; later fc1 split-K partials
__device__ float g_qkv[BS * 3 * EE];    // qkv; attn_out; later fc2/3/4 partials
__device__ float g_ctx[BS * EE];        // ctx; x_flat
__device__ float g_t1[BB * HH];
__device__ float g_t2[BB * HH];
__device__ float g_t3[BB * (HH/2)];
__device__ float g_t4[BB * (HH/4)];
__device__ float g_t5[BB * AA];

// ================= helpers =================
__device__ __forceinline__ uint32_t f2tf32(float x) {
    uint32_t r; asm("cvt.rna.tf32.f32 %0, %1;" : "=r"(r) : "f"(x)); return r;
}
__device__ __forceinline__ uint32_t smem_u32(const void* p) {
    uint32_t a;
    asm("{ .reg .u64 t; cvta.to.shared.u64 t, %1; cvt.u32.u64 %0, t; }" : "=r"(a) : "l"(p));
    return a;
}
#define MMA_TF32(c, a, b) \
    asm volatile("mma.sync.aligned.m16n8k8.row.col.f32.tf32.tf32.f32 " \
        "{%0,%1,%2,%3}, {%4,%5,%6,%7}, {%8,%9}, {%0,%1,%2,%3};" \
        : "+f"((c)[0]), "+f"((c)[1]), "+f"((c)[2]), "+f"((c)[3]) \
        : "r"((a)[0]), "r"((a)[1]), "r"((a)[2]), "r"((a)[3]), \
          "r"((b)[0]), "r"((b)[1]))
__device__ __forceinline__ void cp_async16(uint32_t s, const void* g) {
    asm volatile("cp.async.cg.shared.global [%0], [%1], 16;" :: "r"(s), "l"(g));
}
__device__ __forceinline__ void cp_async4(uint32_t s, const void* g) {
    asm volatile("cp.async.ca.shared.global [%0], [%1], 4;" :: "r"(s), "l"(g));
}
#define CP_COMMIT() asm volatile("cp.async.commit_group;" ::: "memory")
#define CP_WAIT1()  asm volatile("cp.async.wait_group 1;" ::: "memory")
#define CP_WAIT0()  asm volatile("cp.async.wait_group 0;" ::: "memory")

// ============== 3xTF32 mma.sync GEMM:  C = A(M,K) @ W(N,K)^T ==============
// EPI: 0 bias | 3 raw partial (split-K).
// Block tile 256x128, BK=32, 512 threads, warp grid 4x4, warp tile 64x32.
// smem raw fp32, double-buffered: per buf A[256][36] + W[128][36].
#define ROWPAD 36
#define A_FLOATS (256*ROWPAD)          // 9216
#define W_FLOATS (128*ROWPAD)          // 4608
#define BUF_FLOATS (A_FLOATS + W_FLOATS)
#define TG_SMEM (2*BUF_FLOATS*4)       // 110592 B
template<int EPI>
__global__ void __launch_bounds__(512)
tgemm_tf32(const float* __restrict__ A, long lda,
           const float* __restrict__ W, long ldw,
           const float* __restrict__ bias, const float* __restrict__ Res,
           float* __restrict__ C, long ldc, int Kloc, long partStride)
{
    extern __shared__ float smf[];
    const uint32_t sbase = smem_u32(smf);

    const int tid = threadIdx.x;
    const int wid = tid >> 5;
    const int lane = tid & 31;
    const int g   = lane >> 2;
    const int tig = lane & 3;
    const int wm = (wid & 3) * 64;
    const int wn = (wid >> 2) * 32;

    const int m0 = blockIdx.y * 256;
    const int n0 = blockIdx.x * 128;
    const long kbase = (long)blockIdx.z * Kloc;
    float* Cp = C + (EPI == 3 ? (long)blockIdx.z * partStride : 0);
    const bool wal = ((ldw & 3) == 0);
    const int KT = Kloc / 32;

    float acc[4][4][4];
#pragma unroll
    for (int mt = 0; mt < 4; mt++)
#pragma unroll
        for (int nt = 0; nt < 4; nt++)
#pragma unroll
            for (int r = 0; r < 4; r++) acc[mt][nt][r] = 0.f;

    auto prefetch = [&](int kt, int sbi) {
        const long kk = kbase + (long)kt * 32;
        const uint32_t sA = sbase + sbi * (BUF_FLOATS * 4);
        const uint32_t sW = sA + A_FLOATS * 4;
        // A: 256x32 floats = 2048 16B-chunks / 512 threads = 4
#pragma unroll
        for (int i = 0; i < 4; i++) {
            int c = tid + i * 512; int row = c >> 3, q = c & 7;
            cp_async16(sA + (row * ROWPAD + q * 4) * 4,
                       A + (size_t)(m0 + row) * lda + kk + q * 4);
        }
        if (wal) {
#pragma unroll
            for (int i = 0; i < 2; i++) {
                int c = tid + i * 512; int row = c >> 3, q = c & 7;
                cp_async16(sW + (row * ROWPAD + q * 4) * 4,
                           W + (size_t)(n0 + row) * ldw + kk + q * 4);
            }
        } else {
#pragma unroll
            for (int i = 0; i < 8; i++) {
                int c = tid + i * 512; int row = c >> 5, kq = c & 31;
                cp_async4(sW + (row * ROWPAD + kq) * 4,
                          W + (size_t)(n0 + row) * ldw + kk + kq);
            }
        }
    };

    auto compute = [&](int sbi) {
        const float* As = smf + sbi * BUF_FLOATS;
        const float* Ws = As + A_FLOATS;
#pragma unroll
        for (int ks = 0; ks < 4; ks++) {
            const int k0 = ks * 8;
            uint32_t bh[4][2], bl[4][2];
#pragma unroll
            for (int nt = 0; nt < 4; nt++) {
                const int c = (wn + nt * 8 + g) * ROWPAD + k0 + tig;
                float r0 = Ws[c];
                float r1 = Ws[c + 4];
                uint32_t h0 = f2tf32(r0);
                uint32_t h1 = f2tf32(r1);
                bh[nt][0] = h0; bl[nt][0] = f2tf32(r0 - __uint_as_float(h0));
                bh[nt][1] = h1; bl[nt][1] = f2tf32(r1 - __uint_as_float(h1));
            }
#pragma unroll
            for (int mt = 0; mt < 4; mt++) {
                const int r = (wm + mt * 16 + g) * ROWPAD + k0 + tig;
                float x0 = As[r];
                float x1 = As[r + 8 * ROWPAD];
                float x2 = As[r + 4];
                float x3 = As[r + 8 * ROWPAD + 4];
                uint32_t ah[4], al[4];
                ah[0] = f2tf32(x0); al[0] = f2tf32(x0 - __uint_as_float(ah[0]));
                ah[1] = f2tf32(x1); al[1] = f2tf32(x1 - __uint_as_float(ah[1]));
                ah[2] = f2tf32(x2); al[2] = f2tf32(x2 - __uint_as_float(ah[2]));
                ah[3] = f2tf32(x3); al[3] = f2tf32(x3 - __uint_as_float(ah[3]));
#pragma unroll
                for (int nt = 0; nt < 4; nt++) {
                    MMA_TF32(acc[mt][nt], al, bh[nt]);  // lo*hi
                    MMA_TF32(acc[mt][nt], ah, bl[nt]);  // hi*lo
                    MMA_TF32(acc[mt][nt], ah, bh[nt]);  // hi*hi
                }
            }
        }
    };

    // prologue
    prefetch(0, 0); CP_COMMIT();
    prefetch(1, 1); CP_COMMIT();
    CP_WAIT1();
    __syncthreads();

    for (int kt = 0; kt < KT; kt++) {
        compute(kt & 1);
        __syncthreads();                      // all warps done reading this buf
        if (kt + 2 < KT) {
            prefetch(kt + 2, kt & 1); CP_COMMIT();
            CP_WAIT1();                        // tile kt+1 complete
            __syncthreads();
        } else if (kt + 1 < KT) {
            CP_WAIT0();
            __syncthreads();
        }
    }

    // epilogue
#pragma unroll
    for (int mt = 0; mt < 4; mt++) {
#pragma unroll
        for (int nt = 0; nt < 4; nt++) {
            const int col = n0 + wn + nt * 8 + 2 * tig;
            float2 b2 = make_float2(0.f, 0.f);
            if (EPI != 3) b2 = *reinterpret_cast<const float2*>(bias + col);
#pragma unroll
            for (int half = 0; half < 2; half++) {
                const int row = m0 + wm + mt * 16 + g + half * 8;
                float vx = acc[mt][nt][2*half + 0] + b2.x;
                float vy = acc[mt][nt][2*half + 1] + b2.y;
                *reinterpret_cast<float2*>(Cp + (size_t)row * ldc + col) = make_float2(vx, vy);
            }
        }
    }
}

// ============== generic split-K reduce: bias [+relu] [+res] ==============
template<int NSPLIT, int EPI>
__global__ void red_epi(const float* __restrict__ part, long stride,
                        const float* __restrict__ bias, const float* __restrict__ Res,
                        float* __restrict__ out, int N)
{
    const int m = blockIdx.y;
    const int n = blockIdx.x * 256 + threadIdx.x;
    float s = bias[n];
#pragma unroll
    for (int z = 0; z < NSPLIT; z++)
        s += part[(size_t)z * stride + (size_t)m * N + n];
    s = fmaxf(s, 0.f);
    if (EPI == 2) s += Res[(size_t)m * N + n];
    out[(size_t)m * N + n] = s;
}

// ============== fc1 split-K reduce + bias + last_action tail + relu ==============
__global__ void red_fc1(const float* __restrict__ part, const float* __restrict__ la,
                        const float* __restrict__ w1, const float* __restrict__ b1,
                        float* __restrict__ t1)
{
    const int m = blockIdx.y;
    const int n = blockIdx.x * 256 + threadIdx.x;
    __shared__ float las[AA];
    if (threadIdx.x < AA) las[threadIdx.x] = la[m * AA + threadIdx.x];
    __syncthreads();
    float s = b1[n];
#pragma unroll
    for (int z = 0; z < FC1_SPLITS; z++)
        s += part[(size_t)z * (BB * HH) + (size_t)m * HH + n];
    const float* w = w1 + (size_t)n * LDW1 + KFLAT;
    float acc = 0.f;
    for (int j = 0; j < AA; j++) acc += las[j] * w[j];
    t1[(size_t)m * HH + n] = fmaxf(s + acc, 0.f);
}

// ================= fp32 fallback GEMM (fc5 only, N=129 ragged) =================
template<int BM, int BN, int BK, int TM, int TN>
__global__ void __launch_bounds__((BM/TM)*(BN/TN))
gemm_tn(const float* __restrict__ A, int lda,
        const float* __restrict__ W, int ldw,
        const float* __restrict__ bias,
        float* __restrict__ C, int M, int N, int K)
{
    constexpr int THREADS = (BM/TM)*(BN/TN);
    constexpr int KV = BK / 4;
    __shared__ __align__(16) float As[BK][BM];
    __shared__ __align__(16) float Ws[BK][BN];
    const int tid = threadIdx.x;
    const int m0 = blockIdx.y * BM;
    const int n0 = blockIdx.x * BN;
    const int tnx = tid % (BN/TN);
    const int tmy = tid / (BN/TN);
    float acc[TM][TN];
#pragma unroll
    for (int i = 0; i < TM; i++)
#pragma unroll
        for (int j = 0; j < TN; j++) acc[i][j] = 0.f;
    for (int k0 = 0; k0 < K; k0 += BK) {
#pragma unroll
        for (int it = 0; it < (BM*KV)/THREADS; it++) {
            int v = tid + it * THREADS; int row = v / KV, kq = v % KV;
            float4 f = make_float4(0.f,0.f,0.f,0.f);
            if (m0 + row < M) f = *reinterpret_cast<const float4*>(A + (size_t)(m0+row)*lda + k0 + kq*4);
            As[kq*4+0][row]=f.x; As[kq*4+1][row]=f.y; As[kq*4+2][row]=f.z; As[kq*4+3][row]=f.w;
        }
#pragma unroll
        for (int it = 0; it < (BN*KV)/THREADS; it++) {
            int v = tid + it * THREADS; int row = v / KV, kq = v % KV;
            float4 f = make_float4(0.f,0.f,0.f,0.f);
            if (n0 + row < N) f = *reinterpret_cast<const float4*>(W + (size_t)(n0+row)*ldw + k0 + kq*4);
            Ws[kq*4+0][row]=f.x; Ws[kq*4+1][row]=f.y; Ws[kq*4+2][row]=f.z; Ws[kq*4+3][row]=f.w;
        }
        __syncthreads();
#pragma unroll
        for (int kk = 0; kk < BK; kk++) {
            float a[TM], w[TN];
#pragma unroll
            for (int i = 0; i < TM; i++) a[i] = As[kk][tmy*TM + i];
#pragma unroll
            for (int j = 0; j < TN; j++) w[j] = Ws[kk][tnx*TN + j];
#pragma unroll
            for (int i = 0; i < TM; i++)
#pragma unroll
                for (int j = 0; j < TN; j++) acc[i][j] += a[i] * w[j];
        }
        __syncthreads();
    }
#pragma unroll
    for (int i = 0; i < TM; i++) {
        int m = m0 + tmy*TM + i; if (m >= M) continue;
#pragma unroll
        for (int j = 0; j < TN; j++) {
            int n = n0 + tnx*TN + j; if (n >= N) continue;
            C[(size_t)m * N + n] = acc[i][j] + bias[n];
        }
    }
}

// ================= attention: one block per (batch, head), float4 ILP =================
#define ATTN_SMEM ((2*128*64 + 128*129)*4)
__global__ void __launch_bounds__(128)
attn_kernel(const float* __restrict__ qkv, float* __restrict__ ctx)
{
    const int b = blockIdx.x / NH;
    const int h = blockIdx.x % NH;
    extern __shared__ float sm[];
    float* ks = sm;
    float* vs = sm + 128*64;
    float* sc = sm + 2*128*64;
    const int tid = threadIdx.x;

    const size_t base = (size_t)b * SS * (3*EE) + (size_t)h * HD;
    for (int idx = tid; idx < SS*HD; idx += 128) {
        int s = idx >> 6, d = idx & 63;
        const float* p = qkv + base + (size_t)s * (3*EE);
        ks[s*64 + d] = p[EE + d];
        vs[s*64 + d] = p[2*EE + d];
    }
    float4 q4[16];
    {
        const float4* qp = reinterpret_cast<const float4*>(qkv + base + (size_t)tid * (3*EE));
#pragma unroll
        for (int i = 0; i < 16; i++) {
            float4 t = qp[i];
            q4[i] = make_float4(t.x*0.125f, t.y*0.125f, t.z*0.125f, t.w*0.125f);
        }
    }
    __syncthreads();

    float mx = -1e30f;
    for (int j = 0; j < SS; j++) {
        const float4* kp = reinterpret_cast<const float4*>(ks + j*64);
        float4 s4 = make_float4(0.f, 0.f, 0.f, 0.f);
#pragma unroll
        for (int i = 0; i < 16; i++) {
            float4 kv = kp[i];
            s4.x = fmaf(q4[i].x, kv.x, s4.x);
            s4.y = fmaf(q4[i].y, kv.y, s4.y);
            s4.z = fmaf(q4[i].z, kv.z, s4.z);
            s4.w = fmaf(q4[i].w, kv.w, s4.w);
        }
        float s = (s4.x + s4.y) + (s4.z + s4.w);
        sc[tid*129 + j] = s;
        mx = fmaxf(mx, s);
    }
    float sum = 0.f;
    for (int j = 0; j < SS; j++) {
        float e = expf(sc[tid*129 + j] - mx);
        sc[tid*129 + j] = e;
        sum += e;
    }
    const float inv = 1.f / sum;

    float4 a4[16];
#pragma unroll
    for (int i = 0; i < 16; i++) a4[i] = make_float4(0.f, 0.f, 0.f, 0.f);
    for (int j = 0; j < SS; j++) {
        const float w = sc[tid*129 + j] * inv;
        const float4* vp = reinterpret_cast<const float4*>(vs + j*64);
#pragma unroll
        for (int i = 0; i < 16; i++) {
            float4 vv = vp[i];
            a4[i].x = fmaf(w, vv.x, a4[i].x);
            a4[i].y = fmaf(w, vv.y, a4[i].y);
            a4[i].z = fmaf(w, vv.z, a4[i].z);
            a4[i].w = fmaf(w, vv.w, a4[i].w);
        }
    }
    float4* outp = reinterpret_cast<float4*>(ctx + ((size_t)b * SS + tid) * EE + h * HD);
#pragma unroll
    for (int i = 0; i < 16; i++) outp[i] = a4[i];
}

// ================= block reduce / layernorm =================
__device__ __forceinline__ float block_reduce_sum(float v)
{
    __shared__ float shm[32];
    int lane = threadIdx.x & 31, wid = threadIdx.x >> 5;
#pragma unroll
    for (int o = 16; o > 0; o >>= 1) v += __shfl_down_sync(0xffffffffu, v, o);
    if (lane == 0) shm[wid] = v;
    __syncthreads();
    float r = (threadIdx.x < (blockDim.x >> 5)) ? shm[threadIdx.x] : 0.f;
    if (wid == 0) {
#pragma unroll
        for (int o = 16; o > 0; o >>= 1) r += __shfl_down_sync(0xffffffffu, r, o);
        if (lane == 0) shm[0] = r;
    }
    __syncthreads();
    r = shm[0];
    __syncthreads();
    return r;
}

template<bool ADD>
__global__ void ln_kernel(const float* __restrict__ X, const float* __restrict__ Y,
                          const float* __restrict__ g, const float* __restrict__ be,
                          float* __restrict__ out, int D)
{
    const size_t row = blockIdx.x;
    const float* x = X + row * D;
    const float* y = ADD ? (Y + row * D) : nullptr;
    float s = 0.f, s2 = 0.f;
    for (int i = threadIdx.x; i < D; i += blockDim.x) {
        float v = x[i];
        if (ADD) v += y[i];
        s += v; s2 += v * v;
    }
    float S  = block_reduce_sum(s);
    float S2 = block_reduce_sum(s2);
    float mean = S / (float)D;
    float var  = S2 / (float)D - mean * mean;
    float inv  = rsqrtf(var + 1e-5f);
    for (int i = threadIdx.x; i < D; i += blockDim.x) {
        float v = x[i];
        if (ADD) v += y[i];
        out[row * D + i] = (v - mean) * inv * g[i] + be[i];
    }
}

// ================= fc6 + top-K + masked softmax =================
__global__ void head_kernel(const float* __restrict__ t5, const float* __restrict__ la,
                            const float* __restrict__ w6, const float* __restrict__ b6,
                            float* __restrict__ out)
{
    const int b = blockIdx.x;
    __shared__ float cat[2*AA];
    __shared__ float sc[AA];
    __shared__ float red[256];
    const int tid = threadIdx.x;

    for (int i = tid; i < 2*AA; i += 256)
        cat[i] = (i < AA) ? t5[b*AA + i] : la[b*AA + (i - AA)];
    __syncthreads();

    if (tid < AA) {
        float a = b6[tid];
        const float* w = w6 + tid * (2*AA);
        for (int j = 0; j < 2*AA; j++) a += w[j] * cat[j];
        sc[tid] = a;
    }
    __syncthreads();

    bool winner = false; float v = 0.f;
    if (tid < AA) {
        v = sc[tid];
        int cnt = 0;
        for (int j = 0; j < AA; j++) {
            float u = sc[j];
            cnt += (u > v) || (u == v && j < tid);
        }
        winner = cnt < KWIN;
    }
    red[tid] = (tid < AA && winner) ? v : -1e30f;
    __syncthreads();
    for (int s = 128; s > 0; s >>= 1) {
        if (tid < s) red[tid] = fmaxf(red[tid], red[tid + s]);
        __syncthreads();
    }
    float mx = red[0];
    __syncthreads();
    float e = (tid < AA && winner) ? expf(v - mx) : 0.f;
    red[tid] = e;
    __syncthreads();
    for (int s = 128; s > 0; s >>= 1) {
        if (tid < s) red[tid] += red[tid + s];
        __syncthreads();
    }
    float inv = 1.f / red[0];
    if (tid < AA) out[b*AA + tid] = e * inv;
}

// ================= launcher =================
extern "C" void kernel_launch(void* const* d_in, const int* in_sizes, int n_in,
                              void* d_out, int out_size)
{
    const float* hist      = (const float*)d_in[0];
    const float* la        = (const float*)d_in[1];
    const float* embed_w   = (const float*)d_in[2];
    const float* embed_b   = (const float*)d_in[3];
    const float* in_proj_w = (const float*)d_in[4];
    const float* in_proj_b = (const float*)d_in[5];
    const float* out_proj_w= (const float*)d_in[6];
    const float* out_proj_b= (const float*)d_in[7];
    const float* lnorm_g   = (const float*)d_in[8];
    const float* lnorm_b   = (const float*)d_in[9];
    const float* fc1_w     = (const float*)d_in[10];
    const float* fc1_b     = (const float*)d_in[11];
    const float* fc2_w     = (const float*)d_in[12];
    const float* fc2_b     = (const float*)d_in[13];
    const float* ln1_g     = (const float*)d_in[14];
    const float* ln1_b     = (const float*)d_in[15];
    const float* fc3_w     = (const float*)d_in[16];
    const float* fc3_b     = (const float*)d_in[17];
    const float* fc4_w     = (const float*)d_in[18];
    const float* fc4_b     = (const float*)d_in[19];
    const float* fc5_w     = (const float*)d_in[20];
    const float* fc5_b     = (const float*)d_in[21];
    const float* fc6_w     = (const float*)d_in[22];
    const float* fc6_b     = (const float*)d_in[23];
    float* out = (float*)d_out;

    float *h, *qkv, *ctx, *t1, *t2, *t3, *t4, *t5;
    cudaGetSymbolAddress((void**)&h,   g_h);
    cudaGetSymbolAddress((void**)&qkv, g_qkv);
    cudaGetSymbolAddress((void**)&ctx, g_ctx);
    cudaGetSymbolAddress((void**)&t1,  g_t1);
    cudaGetSymbolAddress((void**)&t2,  g_t2);
    cudaGetSymbolAddress((void**)&t3,  g_t3);
    cudaGetSymbolAddress((void**)&t4,  g_t4);
    cudaGetSymbolAddress((void**)&t5,  g_t5);

    cudaFuncSetAttribute(tgemm_tf32<0>, cudaFuncAttributeMaxDynamicSharedMemorySize, TG_SMEM);
    cudaFuncSetAttribute(tgemm_tf32<3>, cudaFuncAttributeMaxDynamicSharedMemorySize, TG_SMEM);
    cudaFuncSetAttribute(attn_kernel,   cudaFuncAttributeMaxDynamicSharedMemorySize, ATTN_SMEM);

    // 1) embed: h = hist @ embed_w^T + b          [65536,640]
    tgemm_tf32<0><<<dim3(EE/128, BS/256, 1), 512, TG_SMEM>>>(
        hist, EE, embed_w, EE, embed_b, nullptr, h, EE, EE, 0);

    // 2) qkv = h @ in_proj_w^T + b                [65536,1920]
    tgemm_tf32<0><<<dim3((3*EE)/128, BS/256, 1), 512, TG_SMEM>>>(
        h, EE, in_proj_w, EE, in_proj_b, nullptr, qkv, 3*EE, EE, 0);

    // 3) attention -> ctx
    attn_kernel<<<BB*NH, 128, ATTN_SMEM>>>(qkv, ctx);

    // 4) attn_out = ctx @ out_proj_w^T + b  (into qkv buffer)
    tgemm_tf32<0><<<dim3(EE/128, BS/256, 1), 512, TG_SMEM>>>(
        ctx, EE, out_proj_w, EE, out_proj_b, nullptr, qkv, EE, EE, 0);

    // 5) x = LN(attn_out + h) -> x_flat (ctx buffer)
    ln_kernel<true><<<BS, 256>>>(qkv, h, lnorm_g, lnorm_b, ctx, EE);

    // 6) fc1 split-K over 81920 aligned cols -> partials in g_h
    tgemm_tf32<3><<<dim3(HH/128, BB/256, FC1_SPLITS), 512, TG_SMEM>>>(
        ctx, KFLAT, fc1_w, LDW1, nullptr, nullptr, h, HH, FC1_KLOC, (long)BB*HH);

    // 7) reduce partials + bias + last_action tail + relu -> t1
    red_fc1<<<dim3(HH/256, BB), 256>>>(h, la, fc1_w, fc1_b, t1);

    // 8) fc2 split-K=8 -> partials in qkv; reduce: t2 = relu(.+b) + t1
    tgemm_tf32<3><<<dim3(HH/128, BB/256, 8), 512, TG_SMEM>>>(
        t1, HH, fc2_w, HH, nullptr, nullptr, qkv, HH, HH/8, (long)BB*HH);
    red_epi<8,2><<<dim3(HH/256, BB), 256>>>(qkv, (long)BB*HH, fc2_b, t1, t2, HH);

    // 9) ln1 in-place on t2
    ln_kernel<false><<<BB, 256>>>(t2, nullptr, ln1_g, ln1_b, t2, HH);

    // 10) fc3 split-K=8: t3 = relu(t2 @ fc3^T + b)  [512,1024]
    tgemm_tf32<3><<<dim3((HH/2)/128, BB/256, 8), 512, TG_SMEM>>>(
        t2, HH, fc3_w, HH, nullptr, nullptr, qkv, HH/2, HH/8, (long)BB*(HH/2));
    red_epi<8,1><<<dim3((HH/2)/256, BB), 256>>>(qkv, (long)BB*(HH/2), fc3_b, nullptr, t3, HH/2);

    // 11) fc4 split-K=8: t4 = relu(t3 @ fc4^T + b)  [512,512]
    tgemm_tf32<3><<<dim3((HH/4)/128, BB/256, 8), 512, TG_SMEM>>>(
        t3, HH/2, fc4_w, HH/2, nullptr, nullptr, qkv, HH/4, (HH/2)/8, (long)BB*(HH/4));
    red_epi<8,1><<<dim3((HH/4)/256, BB), 256>>>(qkv, (long)BB*(HH/4), fc4_b, nullptr, t4, HH/4);

    // 12) fc5 (N=129 ragged -> fp32 path)          [512,129]
    gemm_tn<64,64,16,4,4><<<dim3((AA+63)/64, BB/64), 256>>>(
        t4, HH/4, fc5_w, HH/4, fc5_b, t5, BB, AA, HH/4);

    // 13) fc6 + top-K + masked softmax -> out      [512,129]
    head_kernel<<<BB, 256>>>(t5, la, fc6_w, fc6_b, out);
}